// round 17
// baseline (speedup 1.0000x reference)
#include <cuda_runtime.h>
#include <stdint.h>

#define BB 1024
#define TT 1024
#define KK 48
#define START_TAG 46
#define STOP_TAG 47
#define NEGV (-10000.0f)
#define PADV (-3.0e38f)
#define NT 96                  // 2 sequences per block: 2 threads per tag, x2 seq ILP

// forward-variable scratch: [t][seq][tag] (row t = fv BEFORE step t), +1 pad row
__device__ __align__(16) float g_fv[(size_t)(TT + 1) * BB * KK];

// monotone float -> ordered signed int (exact for all non-NaN floats)
__device__ __forceinline__ int fkey(float f) {
    int i = __float_as_int(f);
    return (i >= 0) ? i : (i ^ 0x7fffffff);
}

// exact argmax over 48 candidates: lane l holds index l (sa) and 32+l (sb, PADV
// for l>=16). Ties -> lowest index (matches jnp.argmax first occurrence).
__device__ __forceinline__ int argmax48(float sa, float sb, float* bout) {
    int ka = fkey(sa), kb = fkey(sb);
    int v = (ka > kb) ? ka : kb;
    int m;
    asm("redux.sync.max.s32 %0, %1, 0xffffffff;" : "=r"(m) : "r"(v));
    unsigned ba = __ballot_sync(0xffffffffu, ka == m);
    unsigned bb = __ballot_sync(0xffffffffu, kb == m);
    int idx = ba ? (__ffs((int)ba) - 1) : (31 + __ffs((int)bb));
    int mi = (m >= 0) ? m : (m ^ 0x7fffffff);
    *bout = __int_as_float(mi);
    return idx;
}

__global__ __launch_bounds__(NT)
void viterbi_kernel(const float* __restrict__ feats,
                    const float* __restrict__ trans,
                    float* __restrict__ out)
{
    __shared__ __align__(16) float fv_sh[2][2][KK];       // [buf][seq][tag]
    __shared__ __align__(16) float trans_sh[KK * KK];
    __shared__ __align__(16) float win_sh[8][2 * KK];     // [k][seq*48+tag]
    __shared__ __align__(16) float feat_sh[2][2][8 * KK]; // [buf][seq][k*48+tag]
    __shared__ uint8_t path_sh[2][TT];

    const int tid = threadIdx.x;
    const int n   = tid >> 1;        // 'next' tag 0..47
    const int c   = tid & 1;         // half: prevs [c*24, c*24+24)
    const int s0  = blockIdx.x * 2;  // grid == BB/2; seqs s0, s0+1

    // stage transitions into smem (used only by backtrack)
    for (int i2 = tid; i2 < KK * KK; i2 += NT) trans_sh[i2] = trans[i2];

    // this thread's 24 transition entries (shared by both sequences)
    float tr[24];
#pragma unroll
    for (int k = 0; k < 24; k++) tr[k] = trans[n * KK + c * 24 + k];

    const float* fA = feats + (size_t)s0 * TT * KK;        // seq A window base
    const float* fB = feats + (size_t)(s0 + 1) * TT * KK;  // seq B window base
    // window 0 feats: one coalesced float4 per thread per sequence
    {
        float4 va = *reinterpret_cast<const float4*>(fA + tid * 4);
        float4 vb = *reinterpret_cast<const float4*>(fB + tid * 4);
        reinterpret_cast<float4*>(&feat_sh[0][0][0])[tid] = va;
        reinterpret_cast<float4*>(&feat_sh[0][1][0])[tid] = vb;
    }
    if (c == 0) {
        float iv = (n == START_TAG) ? 0.0f : NEGV;
        fv_sh[0][0][n] = iv;
        fv_sh[0][1][n] = iv;
    }
    __syncthreads();

    const size_t RSTR = (size_t)BB * KK;
    // flush indexing: 192 float4 (8 rows x 96 floats, both seqs contiguous)
    // thread handles f4 idx {tid, tid+96}
    const int r0 = tid / 24, c0 = tid % 24;             // idx = tid
    const int r1 = (tid + NT) / 24, c1 = (tid + NT) % 24;

    // ---------------- forward pass: max-only, 2-seq ILP ----------------
    int buf = 0, fb = 0;
    for (int t0 = 0; t0 < TT; t0 += 8) {
        const int tnx = (t0 + 8 < TT) ? (t0 + 8) : t0;   // clamped prefetch
        float4 nfa = *reinterpret_cast<const float4*>(fA + (size_t)tnx * KK + tid * 4);
        float4 nfb = *reinterpret_cast<const float4*>(fB + (size_t)tnx * KK + tid * 4);
#pragma unroll
        for (int k = 0; k < 8; k++) {
            float featA = feat_sh[fb][0][k * KK + n];
            float featB = feat_sh[fb][1][k * KK + n];

            const float4* fvrA =
                reinterpret_cast<const float4*>(&fv_sh[buf][0][c * 24]);
            const float4* fvrB =
                reinterpret_cast<const float4*>(&fv_sh[buf][1][c * 24]);
            float4 a0 = fvrA[0], z0 = fvrB[0];
            float bA0 = a0.x + tr[0], bA1 = a0.y + tr[1];
            float bA2 = a0.z + tr[2], bA3 = a0.w + tr[3];
            float bB0 = z0.x + tr[0], bB1 = z0.y + tr[1];
            float bB2 = z0.z + tr[2], bB3 = z0.w + tr[3];
#pragma unroll
            for (int q = 1; q < 6; q++) {
                float4 wa = fvrA[q], wb = fvrB[q];
                bA0 = fmaxf(bA0, wa.x + tr[4 * q + 0]);
                bA1 = fmaxf(bA1, wa.y + tr[4 * q + 1]);
                bA2 = fmaxf(bA2, wa.z + tr[4 * q + 2]);
                bA3 = fmaxf(bA3, wa.w + tr[4 * q + 3]);
                bB0 = fmaxf(bB0, wb.x + tr[4 * q + 0]);
                bB1 = fmaxf(bB1, wb.y + tr[4 * q + 1]);
                bB2 = fmaxf(bB2, wb.z + tr[4 * q + 2]);
                bB3 = fmaxf(bB3, wb.w + tr[4 * q + 3]);
            }
            float bA = fmaxf(fmaxf(bA0, bA1), fmaxf(bA2, bA3));
            float bB = fmaxf(fmaxf(bB0, bB1), fmaxf(bB2, bB3));
            bA = fmaxf(bA, __shfl_xor_sync(0xffffffffu, bA, 1));
            bB = fmaxf(bB, __shfl_xor_sync(0xffffffffu, bB, 1));
            float nvA = bA + featA;
            float nvB = bB + featB;
            if (c == 0) {
                fv_sh[buf ^ 1][0][n] = nvA;    // critical path
                fv_sh[buf ^ 1][1][n] = nvB;
            } else {
                win_sh[k][n] = nvA;            // staging on idle half
                win_sh[k][KK + n] = nvB;
            }
            __syncthreads();
            buf ^= 1;
        }
        // stage next window's feats + coalesced g_fv flush (both seqs)
        reinterpret_cast<float4*>(&feat_sh[fb ^ 1][0][0])[tid] = nfa;
        reinterpret_cast<float4*>(&feat_sh[fb ^ 1][1][0])[tid] = nfb;
        {
            float4 v0 = reinterpret_cast<const float4*>(&win_sh[r0][0])[c0];
            float4 v1 = reinterpret_cast<const float4*>(&win_sh[r1][0])[c1];
            float* d0 = g_fv + (size_t)(t0 + 1 + r0) * RSTR
                      + (size_t)s0 * KK + c0 * 4;
            float* d1 = g_fv + (size_t)(t0 + 1 + r1) * RSTR
                      + (size_t)s0 * KK + c1 * 4;
            *reinterpret_cast<float4*>(d0) = v0;
            *reinterpret_cast<float4*>(d1) = v1;
        }
        __syncthreads();   // protects win_sh reuse + feat_sh availability
        fb ^= 1;
    }

    // ------------- terminal + backtrack (warp w -> seq s0+w) -------------
    const int wid = tid >> 5;
    if (wid < 2) {
        const int l = tid & 31;
        const int seq = s0 + wid;
        float fa = fv_sh[buf][wid][l];
        float fb2 = (l < 16) ? fv_sh[buf][wid][32 + l] : 0.0f;
        float sa = fa + trans_sh[STOP_TAG * KK + l];
        float sb = (l < 16) ? (fb2 + trans_sh[STOP_TAG * KK + 32 + l]) : PADV;
        float best;
        int tag = argmax48(sa, sb, &best);
        if (l == 0) out[seq] = best;

        const float* rowbase = g_fv + (size_t)seq * KK;
        // 3-deep register prefetch of fv rows hides DRAM/L2 latency
        float a0 = rowbase[(size_t)(TT - 1) * RSTR + l];
        float e0 = (l < 16) ? rowbase[(size_t)(TT - 1) * RSTR + 32 + l] : 0.0f;
        float a1 = rowbase[(size_t)(TT - 2) * RSTR + l];
        float e1 = (l < 16) ? rowbase[(size_t)(TT - 2) * RSTR + 32 + l] : 0.0f;
        float a2 = rowbase[(size_t)(TT - 3) * RSTR + l];
        float e2 = (l < 16) ? rowbase[(size_t)(TT - 3) * RSTR + 32 + l] : 0.0f;

#define BT_STEP(T_, AA, EE, PF)                                              \
        {                                                                    \
            if (l == 0) path_sh[wid][(T_)] = (uint8_t)tag;                   \
            float s_a = AA + trans_sh[tag * KK + l];                         \
            float s_b = (l < 16) ? (EE + trans_sh[tag * KK + 32 + l]) : PADV;\
            int rpf = ((PF) < 1) ? 1 : (PF);                                 \
            AA = rowbase[(size_t)rpf * RSTR + l];                            \
            EE = (l < 16) ? rowbase[(size_t)rpf * RSTR + 32 + l] : 0.0f;     \
            float bv;                                                        \
            tag = argmax48(s_a, s_b, &bv);                                   \
        }

        for (int t = TT - 1; t >= 3; t -= 3) {   // 1023 steps, divisible by 3
            BT_STEP(t,     a0, e0, t - 3)
            BT_STEP(t - 1, a1, e1, t - 4)
            BT_STEP(t - 2, a2, e2, t - 5)
        }
        if (l == 0) path_sh[wid][0] = (uint8_t)tag;
#undef BT_STEP
    }
    __syncthreads();

    // ---------------- coalesced path dump (both seqs) ----------------
    for (int idx = tid; idx < 2 * TT; idx += NT) {
        int s = idx >> 10;
        int t = idx & (TT - 1);
        out[BB + (size_t)(s0 + s) * TT + t] = (float)path_sh[s][t];
    }
}

extern "C" void kernel_launch(void* const* d_in, const int* in_sizes, int n_in,
                              void* d_out, int out_size) {
    (void)in_sizes; (void)n_in; (void)out_size;
    const float* feats = (const float*)d_in[0];
    const float* trans = (const float*)d_in[1];
    float* out = (float*)d_out;
    viterbi_kernel<<<BB / 2, NT>>>(feats, trans, out);
}